// round 2
// baseline (speedup 1.0000x reference)
#include <cuda_runtime.h>
#include <cstdint>
#include <cstddef>

// ---------------------------------------------------------------------------
// Problem constants (fixed by setup_inputs)
// ---------------------------------------------------------------------------
constexpr int B_ = 4, N_ = 2048, D_ = 64;
constexpr float GAMMA_ = 5.0f;
constexpr float TAU_F = 0.8f, TAU_C = 0.7f, TAU_P = 0.5f;

// ---------------------------------------------------------------------------
// Scratch (device globals -- allocation-free per harness rules)
// ---------------------------------------------------------------------------
__device__ float  g_nf[B_ * N_ * D_];          // normalized features
__device__ float4 g_f4[B_ * N_];               // flow.xyz, |flow|
__device__ float4 g_p4[B_ * N_];               // pts.xyz, mask
__device__ float4 g_c4[B_ * N_];               // colors/255, label bits
__device__ float  g_fs[(size_t)B_ * N_ * N_];  // 64 MB Gram scratch for SAM pass 2
__device__ float  g_rowA[B_ * N_];             // per-row combined within-sample loss
__device__ float  g_neg[B_ * N_];              // SAM negsum per row
__device__ float  g_posfs[B_ * N_];            // SAM sum of fs over positive pairs
__device__ float  g_possum[B_ * N_];           // SAM positive count
__device__ float  g_rowSam[B_ * N_];           // per-row SAM nll

// ---------------------------------------------------------------------------
// Kernel 0: preprocess. One warp per point.
// ---------------------------------------------------------------------------
__global__ void k_pre(const float* __restrict__ feat,
                      const float* __restrict__ flow,
                      const float* __restrict__ pts,
                      const int*   __restrict__ cols,
                      const int*   __restrict__ sam,
                      const unsigned char* __restrict__ mask) {
    int p    = blockIdx.x * (blockDim.x >> 5) + (threadIdx.x >> 5);
    int lane = threadIdx.x & 31;
    if (p >= B_ * N_) return;

    const float2 v = ((const float2*)(feat + (size_t)p * D_))[lane];
    float s = v.x * v.x + v.y * v.y;
    #pragma unroll
    for (int o = 16; o; o >>= 1) s += __shfl_xor_sync(0xffffffffu, s, o);
    float inv = 1.0f / (sqrtf(s) + 1e-7f);
    ((float2*)(g_nf + (size_t)p * D_))[lane] = make_float2(v.x * inv, v.y * inv);

    if (lane == 0) {
        float fx = flow[p * 3], fy = flow[p * 3 + 1], fz = flow[p * 3 + 2];
        g_f4[p] = make_float4(fx, fy, fz, sqrtf(fx * fx + fy * fy + fz * fz));
        g_p4[p] = make_float4(pts[p * 3], pts[p * 3 + 1], pts[p * 3 + 2],
                              mask[p] ? 1.0f : 0.0f);
        g_c4[p] = make_float4(cols[p * 3]     * (1.0f / 255.0f),
                              cols[p * 3 + 1] * (1.0f / 255.0f),
                              cols[p * 3 + 2] * (1.0f / 255.0f),
                              __int_as_float(sam[p]));
    }
}

// ---------------------------------------------------------------------------
// Kernel 1: the heavy pair kernel.
//  Block = 256 threads = 8 warps; each warp owns one row n.
//  m loops over 64-column smem tiles; lane strides m by 32.
//  Feature tiles padded to 68 floats/row: LDS.128 column reads hit the
//  structural 4-cycle crossbar floor with no extra conflicts.
// ---------------------------------------------------------------------------
constexpr int ROWS = 8, MT = 64, PAD = 68;

__global__ void __launch_bounds__(256) k_pair() {
    const int b    = blockIdx.y;
    const int row0 = blockIdx.x * ROWS;
    const int r    = threadIdx.x >> 5;
    const int lane = threadIdx.x & 31;
    const int n    = row0 + r;

    __shared__ float  sRow[ROWS * PAD];
    __shared__ float  sCol[MT * PAD];
    __shared__ float4 sRF[ROWS], sRP[ROWS], sRC[ROWS];
    __shared__ float4 sCF[MT],   sCP[MT],   sCC[MT];

    const float* nfB = g_nf + (size_t)b * N_ * D_;

    // load row-block features (8 rows x 16 float4)
    if (threadIdx.x < ROWS * 16) {
        int rr = threadIdx.x >> 4, k = threadIdx.x & 15;
        ((float4*)(sRow + rr * PAD))[k] =
            ((const float4*)(nfB + (size_t)(row0 + rr) * D_))[k];
    }
    if (threadIdx.x < ROWS) {
        int p = b * N_ + row0 + threadIdx.x;
        sRF[threadIdx.x] = g_f4[p];
        sRP[threadIdx.x] = g_p4[p];
        sRC[threadIdx.x] = g_c4[p];
    }
    __syncthreads();

    const float4 fr = sRF[r], pr = sRP[r], cr = sRC[r];
    const int labr = __float_as_int(cr.w);

    float spf = 0.f, smf = 0.f, spc = 0.f, smc = 0.f, spp = 0.f, smp = 0.f;
    float neg = 0.f, psum = 0.f, pfs = 0.f;

    for (int mt = 0; mt < N_; mt += MT) {
        __syncthreads();
        // load 64-column feature tile: 1024 float4, 4 per thread
        #pragma unroll
        for (int i = 0; i < 4; i++) {
            int idx = threadIdx.x + 256 * i;
            int mm = idx >> 4, k = idx & 15;
            ((float4*)(sCol + mm * PAD))[k] =
                ((const float4*)(nfB + (size_t)(mt + mm) * D_))[k];
        }
        if (threadIdx.x < MT) {
            int p = b * N_ + mt + threadIdx.x;
            sCF[threadIdx.x] = g_f4[p];
            sCP[threadIdx.x] = g_p4[p];
            sCC[threadIdx.x] = g_c4[p];
        }
        __syncthreads();

        #pragma unroll
        for (int j = 0; j < MT / 32; j++) {
            const int ml = lane + 32 * j;
            const int m  = mt + ml;

            const float4* arow = (const float4*)(sRow + r * PAD);
            const float4* acol = (const float4*)(sCol + ml * PAD);
            float fs = 0.f;
            #pragma unroll
            for (int k = 0; k < 16; k++) {
                float4 a = arow[k], c = acol[k];
                fs = fmaf(a.x, c.x, fs);
                fs = fmaf(a.y, c.y, fs);
                fs = fmaf(a.z, c.z, fs);
                fs = fmaf(a.w, c.w, fs);
            }

            const float4 fm = sCF[ml], pm = sCP[ml], cm = sCC[ml];
            const float msk = pr.w * pm.w;

            // flow cosine sim (exact eps semantics of the reference)
            float fsim = __fdividef(fr.x * fm.x + fr.y * fm.y + fr.z * fm.z,
                                    fr.w * fm.w + 1e-8f) * msk;
            // color sim: 1 - |c_n - c_m| / sqrt(3)
            float dx = cr.x - cm.x, dy = cr.y - cm.y, dz = cr.z - cm.z;
            float d2 = fmaxf(dx * dx + dy * dy + dz * dz, 1e-30f);
            float csim = (1.0f - d2 * rsqrtf(d2) * 0.57735026918962576f) * msk;
            // proximity sim: exp(-dist / (2*sigma^2)) = exp(-50*dist)
            dx = pr.x - pm.x; dy = pr.y - pm.y; dz = pr.z - pm.z;
            float e2 = fmaxf(dx * dx + dy * dy + dz * dz, 1e-30f);
            float psim = __expf(-50.0f * (e2 * rsqrtf(e2))) * msk;

            const float emfs = __expf(-fs);   // shared: exp(-fs)

            // within-sample terms: g_minus = 1-g_plus; exp(-fs*g_minus)=exp(-fs)*exp(fs*g_plus)
            {
                float a  = __expf(GAMMA_ * (TAU_F - fsim));
                float gp = __fdividef(1.0f, 1.0f + a);
                float ep = __expf(fs * gp);
                spf += ep; smf = fmaf(emfs, ep, smf);
            }
            {
                float a  = __expf(GAMMA_ * (TAU_C - csim));
                float gp = __fdividef(1.0f, 1.0f + a);
                float ep = __expf(fs * gp);
                spc += ep; smc = fmaf(emfs, ep, smc);
            }
            {
                float a  = __expf(GAMMA_ * (TAU_P - psim));
                float gp = __fdividef(1.0f, 1.0f + a);
                float ep = __expf(fs * gp);
                spp += ep; smp = fmaf(emfs, ep, smp);
            }

            // SAM pass-1 accumulators
            float efs = __expf(fs);
            int labm = __float_as_int(cm.w);
            float pos = (labr == labm) ? 1.0f : 0.0f;
            neg  = fmaf(efs, 1.0f - pos, neg);
            psum += pos;
            pfs  = fmaf(fs, pos, pfs);

            g_fs[(size_t)(b * N_ + n) * (size_t)N_ + (size_t)m] = fs;
        }
    }

    // warp reduction (one warp == one row), split into two groups to cut
    // simultaneous live registers
    #pragma unroll
    for (int o = 16; o; o >>= 1) {
        spf  += __shfl_xor_sync(0xffffffffu, spf,  o);
        smf  += __shfl_xor_sync(0xffffffffu, smf,  o);
        spc  += __shfl_xor_sync(0xffffffffu, spc,  o);
        smc  += __shfl_xor_sync(0xffffffffu, smc,  o);
        spp  += __shfl_xor_sync(0xffffffffu, spp,  o);
    }
    #pragma unroll
    for (int o = 16; o; o >>= 1) {
        smp  += __shfl_xor_sync(0xffffffffu, smp,  o);
        neg  += __shfl_xor_sync(0xffffffffu, neg,  o);
        psum += __shfl_xor_sync(0xffffffffu, psum, o);
        pfs  += __shfl_xor_sync(0xffffffffu, pfs,  o);
    }
    if (lane == 0) {
        int bn = b * N_ + n;
        float lpp = __logf(1.0f + spf) + __logf(1.0f + smf)
                  + __logf(1.0f + spc) + __logf(1.0f + smc)
                  + __logf(1.0f + spp) + __logf(1.0f + smp);
        g_rowA[bn]   = lpp * pr.w;
        g_neg[bn]    = neg;
        g_possum[bn] = psum;
        g_posfs[bn]  = pfs;
    }
}

// ---------------------------------------------------------------------------
// Kernel 2: SAM pass-2 (log term over positive pairs). One block per row.
// ---------------------------------------------------------------------------
__global__ void __launch_bounds__(128) k_sam(const int* __restrict__ sam) {
    const int bn = blockIdx.x;
    const int b  = bn >> 11;  // N_ == 2048
    const int labn = sam[bn];
    const float neg = g_neg[bn];
    const float* fsrow = g_fs + (size_t)bn * N_;
    const int* labs = sam + b * N_;

    float acc = 0.f;
    for (int m = threadIdx.x; m < N_; m += 128) {
        int   lm = labs[m];
        float fs = fsrow[m];
        if (lm == labn) acc += __logf(__expf(fs) + neg);
    }
    #pragma unroll
    for (int o = 16; o; o >>= 1) acc += __shfl_xor_sync(0xffffffffu, acc, o);
    __shared__ float sred[4];
    if ((threadIdx.x & 31) == 0) sred[threadIdx.x >> 5] = acc;
    __syncthreads();
    if (threadIdx.x == 0) {
        float t = sred[0] + sred[1] + sred[2] + sred[3];
        // nll_row = (sum_pos log(denom) - sum_pos fs) / pos_count
        g_rowSam[bn] = (t - g_posfs[bn]) / g_possum[bn];
    }
}

// ---------------------------------------------------------------------------
// Kernel 3: final reduction (double precision), writes the scalar.
// ---------------------------------------------------------------------------
__global__ void k_final(const unsigned char* __restrict__ mask,
                        float* __restrict__ out) {
    __shared__ double red[256];
    const int tid = threadIdx.x;

    double accA[B_] = {0, 0, 0, 0};
    double accV[B_] = {0, 0, 0, 0};
    double accS = 0.0;
    for (int i = tid; i < B_ * N_; i += 256) {
        int b = i >> 11;
        accA[b] += (double)g_rowA[i];
        accV[b] += mask[i] ? 1.0 : 0.0;
        accS    += (double)g_rowSam[i];
    }

    auto reduce = [&](double v) -> double {
        red[tid] = v;
        __syncthreads();
        for (int s = 128; s; s >>= 1) {
            if (tid < s) red[tid] += red[tid + s];
            __syncthreads();
        }
        double r = red[0];
        __syncthreads();
        return r;
    };

    double sA0 = reduce(accA[0]), sA1 = reduce(accA[1]);
    double sA2 = reduce(accA[2]), sA3 = reduce(accA[3]);
    double sV0 = reduce(accV[0]), sV1 = reduce(accV[1]);
    double sV2 = reduce(accV[2]), sV3 = reduce(accV[3]);
    double sS  = reduce(accS);

    if (tid == 0) {
        double core = sA0 / sV0 + sA1 / sV1 + sA2 / sV2 + sA3 / sV3;
        double total = -core / (double)B_ + sS / ((double)B_ * (double)N_);
        out[0] = (float)total;
    }
}

// ---------------------------------------------------------------------------
// Launcher
// ---------------------------------------------------------------------------
extern "C" void kernel_launch(void* const* d_in, const int* in_sizes, int n_in,
                              void* d_out, int out_size) {
    const float* feat = (const float*)d_in[0];
    const float* flow = (const float*)d_in[1];
    const float* pts  = (const float*)d_in[2];
    const int*   cols = (const int*)d_in[3];
    const int*   sam  = (const int*)d_in[4];
    const unsigned char* mask = (const unsigned char*)d_in[5];

    k_pre<<<(B_ * N_) / 8, 256>>>(feat, flow, pts, cols, sam, mask);
    dim3 g1(N_ / ROWS, B_);
    k_pair<<<g1, 256>>>();
    k_sam<<<B_ * N_, 128>>>(sam);
    k_final<<<1, 256>>>(mask, (float*)d_out);
}

// round 3
// speedup vs baseline: 1.1322x; 1.1322x over previous
#include <cuda_runtime.h>
#include <cstdint>
#include <cstddef>

// ---------------------------------------------------------------------------
// Problem constants (fixed by setup_inputs)
// ---------------------------------------------------------------------------
constexpr int B_ = 4, N_ = 2048, D_ = 64;
constexpr float GAMMA_ = 5.0f;
constexpr float TAU_F = 0.8f, TAU_C = 0.7f, TAU_P = 0.5f;

// ---------------------------------------------------------------------------
// Scratch (device globals -- allocation-free per harness rules)
// ---------------------------------------------------------------------------
__device__ float  g_nf[B_ * N_ * D_];   // normalized features
__device__ float4 g_f4[B_ * N_];        // flow.xyz, |flow|
__device__ float4 g_p4[B_ * N_];        // pts.xyz, mask
__device__ float4 g_c4[B_ * N_];        // colors/255, label bits
__device__ float  g_rowA[B_ * N_];      // per-row combined within-sample loss
__device__ float  g_neg[B_ * N_];       // SAM negsum per row
__device__ float  g_posfs[B_ * N_];     // SAM sum of fs over positive pairs
__device__ float  g_possum[B_ * N_];    // SAM positive count
__device__ float  g_rowSam[B_ * N_];    // per-row SAM nll

using ull = unsigned long long;

__device__ __forceinline__ void fma2(ull& d, ull a, ull b) {
    asm("fma.rn.f32x2 %0, %1, %2, %0;" : "+l"(d) : "l"(a), "l"(b));
}
__device__ __forceinline__ float2 unpack2(ull v) {
    float2 r;
    asm("mov.b64 {%0, %1}, %2;" : "=f"(r.x), "=f"(r.y) : "l"(v));
    return r;
}

// ---------------------------------------------------------------------------
// Kernel 0: preprocess. One warp per point.
// ---------------------------------------------------------------------------
__global__ void k_pre(const float* __restrict__ feat,
                      const float* __restrict__ flow,
                      const float* __restrict__ pts,
                      const int*   __restrict__ cols,
                      const int*   __restrict__ sam,
                      const unsigned char* __restrict__ mask) {
    int p    = blockIdx.x * (blockDim.x >> 5) + (threadIdx.x >> 5);
    int lane = threadIdx.x & 31;
    if (p >= B_ * N_) return;

    const float2 v = ((const float2*)(feat + (size_t)p * D_))[lane];
    float s = v.x * v.x + v.y * v.y;
    #pragma unroll
    for (int o = 16; o; o >>= 1) s += __shfl_xor_sync(0xffffffffu, s, o);
    float inv = 1.0f / (sqrtf(s) + 1e-7f);
    ((float2*)(g_nf + (size_t)p * D_))[lane] = make_float2(v.x * inv, v.y * inv);

    if (lane == 0) {
        float fx = flow[p * 3], fy = flow[p * 3 + 1], fz = flow[p * 3 + 2];
        g_f4[p] = make_float4(fx, fy, fz, sqrtf(fx * fx + fy * fy + fz * fz));
        g_p4[p] = make_float4(pts[p * 3], pts[p * 3 + 1], pts[p * 3 + 2],
                              mask[p] ? 1.0f : 0.0f);
        g_c4[p] = make_float4(cols[p * 3]     * (1.0f / 255.0f),
                              cols[p * 3 + 1] * (1.0f / 255.0f),
                              cols[p * 3 + 2] * (1.0f / 255.0f),
                              __int_as_float(sam[p]));
    }
}

// ---------------------------------------------------------------------------
// Kernel 1: pair kernel, 4x4 register tiling.
//  Block = 256 threads laid out 16(tx) x 16(ty). Block owns 64 rows, loops
//  over all 2048 columns in 64-wide tiles. Thread computes a 4x4 pair tile.
//  Column feature tile stored XOR-swizzled so the tx-strided LDS hits the
//  2-phase bank floor. Dot product uses packed f32x2 FMA.
// ---------------------------------------------------------------------------
constexpr int PADK = 68;

__global__ void __launch_bounds__(256) k_pair() {
    const int b    = blockIdx.y;
    const int row0 = blockIdx.x * 64;
    const int tid  = threadIdx.x;
    const int tx   = tid & 15, ty = tid >> 4;

    __shared__ float  sA[64][PADK];   // row features  [r][k]
    __shared__ float  sB[64][PADK];   // col features  [m][k], xor-swizzled k4
    __shared__ float4 sRF[64], sRP[64], sRC[64];
    __shared__ float4 sCF[64], sCP[64], sCC[64];

    const float* nfB = g_nf + (size_t)b * N_ * D_;
    const int bn0 = b * N_;

    for (int idx = tid; idx < 1024; idx += 256) {
        int r = idx >> 4, k4 = idx & 15;
        *(float4*)&sA[r][k4 << 2] =
            ((const float4*)(nfB + (size_t)(row0 + r) * D_))[k4];
    }
    if (tid < 64) {
        sRF[tid] = g_f4[bn0 + row0 + tid];
        sRP[tid] = g_p4[bn0 + row0 + tid];
        sRC[tid] = g_c4[bn0 + row0 + tid];
    }

    float acc[4][9];
    #pragma unroll
    for (int i = 0; i < 4; i++)
        #pragma unroll
        for (int q = 0; q < 9; q++) acc[i][q] = 0.f;

    const int xk = tx & 7;

    for (int ct = 0; ct < N_; ct += 64) {
        __syncthreads();
        #pragma unroll
        for (int l = 0; l < 4; l++) {
            int idx = tid + 256 * l;
            int m = idx >> 4, k4 = idx & 15;
            int slot = k4 ^ ((m >> 2) & 7);
            *(float4*)&sB[m][slot << 2] =
                ((const float4*)(nfB + (size_t)(ct + m) * D_))[k4];
        }
        if (tid < 64) {
            sCF[tid] = g_f4[bn0 + ct + tid];
            sCP[tid] = g_p4[bn0 + ct + tid];
            sCC[tid] = g_c4[bn0 + ct + tid];
        }
        __syncthreads();

        // ---- 4x4 dot via packed f32x2 FMA ----
        ull fs2[4][4];
        #pragma unroll
        for (int i = 0; i < 4; i++)
            #pragma unroll
            for (int j = 0; j < 4; j++) fs2[i][j] = 0ULL;

        #pragma unroll
        for (int k4 = 0; k4 < 16; k4++) {
            const int so = (k4 ^ xk) << 2;
            ull b01[4], b23[4];
            #pragma unroll
            for (int j = 0; j < 4; j++) {
                const ull* bp = (const ull*)&sB[4 * tx + j][so];
                b01[j] = bp[0]; b23[j] = bp[1];
            }
            #pragma unroll
            for (int i = 0; i < 4; i++) {
                const ull* ap = (const ull*)&sA[4 * ty + i][k4 << 2];
                ull a01 = ap[0], a23 = ap[1];
                #pragma unroll
                for (int j = 0; j < 4; j++) {
                    fma2(fs2[i][j], a01, b01[j]);
                    fma2(fs2[i][j], a23, b23[j]);
                }
            }
        }
        float fsv[4][4];
        #pragma unroll
        for (int i = 0; i < 4; i++)
            #pragma unroll
            for (int j = 0; j < 4; j++) {
                float2 u = unpack2(fs2[i][j]);
                fsv[i][j] = u.x + u.y;
            }

        // ---- epilogue: per-pair transcendental core ----
        #pragma unroll
        for (int j = 0; j < 4; j++) {
            const int mc = 4 * tx + j;
            const float4 fm = sCF[mc], pm = sCP[mc], cm = sCC[mc];
            const int labm = __float_as_int(cm.w);
            #pragma unroll
            for (int i = 0; i < 4; i++) {
                const int rr = 4 * ty + i;
                const float4 fr = sRF[rr], pr = sRP[rr], cr = sRC[rr];
                const float msk = pr.w * pm.w;
                const float fs  = fsv[i][j];

                float fsim = __fdividef(fr.x * fm.x + fr.y * fm.y + fr.z * fm.z,
                                        fr.w * fm.w + 1e-8f) * msk;
                float dx = cr.x - cm.x, dy = cr.y - cm.y, dz = cr.z - cm.z;
                float d2 = fmaxf(dx * dx + dy * dy + dz * dz, 1e-30f);
                float csim = (1.0f - d2 * rsqrtf(d2) * 0.57735026918962576f) * msk;
                dx = pr.x - pm.x; dy = pr.y - pm.y; dz = pr.z - pm.z;
                float e2 = fmaxf(dx * dx + dy * dy + dz * dz, 1e-30f);
                float psim = __expf(-50.0f * (e2 * rsqrtf(e2))) * msk;

                const float emfs = __expf(-fs);
                float a, gp, ep;
                a = __expf(GAMMA_ * (TAU_F - fsim));
                gp = __fdividef(1.0f, 1.0f + a);
                ep = __expf(fs * gp);
                acc[i][0] += ep; acc[i][1] = fmaf(emfs, ep, acc[i][1]);
                a = __expf(GAMMA_ * (TAU_C - csim));
                gp = __fdividef(1.0f, 1.0f + a);
                ep = __expf(fs * gp);
                acc[i][2] += ep; acc[i][3] = fmaf(emfs, ep, acc[i][3]);
                a = __expf(GAMMA_ * (TAU_P - psim));
                gp = __fdividef(1.0f, 1.0f + a);
                ep = __expf(fs * gp);
                acc[i][4] += ep; acc[i][5] = fmaf(emfs, ep, acc[i][5]);

                float efs = __expf(fs);
                int labr = __float_as_int(cr.w);
                float pos = (labr == labm) ? 1.0f : 0.0f;
                acc[i][6] = fmaf(efs, 1.0f - pos, acc[i][6]);
                acc[i][7] += pos;
                acc[i][8] = fmaf(fs, pos, acc[i][8]);
            }
        }
    }

    // reduce across the 16 tx lanes (xor 8,4,2,1 stays within half-warp group)
    #pragma unroll
    for (int i = 0; i < 4; i++)
        #pragma unroll
        for (int q = 0; q < 9; q++)
            #pragma unroll
            for (int o = 8; o; o >>= 1)
                acc[i][q] += __shfl_xor_sync(0xffffffffu, acc[i][q], o);

    if (tx == 0) {
        #pragma unroll
        for (int i = 0; i < 4; i++) {
            int bn = bn0 + row0 + 4 * ty + i;
            float lpp = __logf(1.0f + acc[i][0]) + __logf(1.0f + acc[i][1])
                      + __logf(1.0f + acc[i][2]) + __logf(1.0f + acc[i][3])
                      + __logf(1.0f + acc[i][4]) + __logf(1.0f + acc[i][5]);
            g_rowA[bn]   = lpp * sRP[4 * ty + i].w;
            g_neg[bn]    = acc[i][6];
            g_possum[bn] = acc[i][7];
            g_posfs[bn]  = acc[i][8];
        }
    }
}

// ---------------------------------------------------------------------------
// Kernel 2: SAM pass-2 -- recompute fs only for positive pairs (~32/row).
//  One warp per row; lanes split the 2048 candidates.
// ---------------------------------------------------------------------------
__global__ void __launch_bounds__(256) k_sam(const int* __restrict__ sam) {
    __shared__ float srow[8][64];
    const int w    = threadIdx.x >> 5;
    const int lane = threadIdx.x & 31;
    const int bn   = blockIdx.x * 8 + w;
    const int bBase = bn & ~(N_ - 1);
    const int labn = sam[bn];
    const float neg = g_neg[bn];

    if (lane < 16)
        ((float4*)srow[w])[lane] = ((const float4*)(g_nf + (size_t)bn * D_))[lane];
    __syncwarp();

    float acc = 0.f;
    for (int c = 0; c < 64; c++) {
        int m = c * 32 + lane;
        if (sam[bBase + m] == labn) {
            const float4* vp = (const float4*)(g_nf + (size_t)(bBase + m) * D_);
            float d = 0.f;
            #pragma unroll
            for (int q = 0; q < 16; q++) {
                float4 v = vp[q], aa = ((float4*)srow[w])[q];
                d = fmaf(aa.x, v.x, fmaf(aa.y, v.y, fmaf(aa.z, v.z, fmaf(aa.w, v.w, d))));
            }
            acc += __logf(__expf(d) + neg);
        }
    }
    #pragma unroll
    for (int o = 16; o; o >>= 1) acc += __shfl_xor_sync(0xffffffffu, acc, o);
    if (lane == 0)
        g_rowSam[bn] = (acc - g_posfs[bn]) / g_possum[bn];
}

// ---------------------------------------------------------------------------
// Kernel 3: final reduction. Static indexing (no local-mem spills).
// ---------------------------------------------------------------------------
__global__ void k_final(const unsigned char* __restrict__ mask,
                        float* __restrict__ out) {
    __shared__ double sh[9];
    if (threadIdx.x < 9) sh[threadIdx.x] = 0.0;
    __syncthreads();

    double A[4] = {0, 0, 0, 0}, V[4] = {0, 0, 0, 0}, S = 0.0;
    #pragma unroll
    for (int it = 0; it < 32; it++) {          // i = tid + 256*it; batch = it>>3 (static)
        int i = threadIdx.x + 256 * it;
        A[it >> 3] += (double)g_rowA[i];
        V[it >> 3] += mask[i] ? 1.0 : 0.0;
        S          += (double)g_rowSam[i];
    }
    #pragma unroll
    for (int o = 16; o; o >>= 1) {
        #pragma unroll
        for (int bb = 0; bb < 4; bb++) {
            A[bb] += __shfl_xor_sync(0xffffffffu, A[bb], o);
            V[bb] += __shfl_xor_sync(0xffffffffu, V[bb], o);
        }
        S += __shfl_xor_sync(0xffffffffu, S, o);
    }
    if ((threadIdx.x & 31) == 0) {
        #pragma unroll
        for (int bb = 0; bb < 4; bb++) {
            atomicAdd(&sh[bb],     A[bb]);
            atomicAdd(&sh[4 + bb], V[bb]);
        }
        atomicAdd(&sh[8], S);
    }
    __syncthreads();
    if (threadIdx.x == 0) {
        double core = sh[0] / sh[4] + sh[1] / sh[5] + sh[2] / sh[6] + sh[3] / sh[7];
        out[0] = (float)(-core / (double)B_ + sh[8] / ((double)B_ * (double)N_));
    }
}

// ---------------------------------------------------------------------------
// Launcher
// ---------------------------------------------------------------------------
extern "C" void kernel_launch(void* const* d_in, const int* in_sizes, int n_in,
                              void* d_out, int out_size) {
    const float* feat = (const float*)d_in[0];
    const float* flow = (const float*)d_in[1];
    const float* pts  = (const float*)d_in[2];
    const int*   cols = (const int*)d_in[3];
    const int*   sam  = (const int*)d_in[4];
    const unsigned char* mask = (const unsigned char*)d_in[5];

    k_pre<<<(B_ * N_) / 8, 256>>>(feat, flow, pts, cols, sam, mask);
    dim3 g1(N_ / 64, B_);
    k_pair<<<g1, 256>>>();
    k_sam<<<(B_ * N_) / 8, 256>>>(sam);
    k_final<<<1, 256>>>(mask, (float*)d_out);
}